// round 12
// baseline (speedup 1.0000x reference)
#include <cuda_runtime.h>
#include <math.h>

#define W    512
#define HGT  512
#define HW   (512*512)
#define TW   64
#define TH   64
#define RMAX 10
#define SW   84               // logical halo tile width
#define SWP  86               // padded s_in row stride (words): u64 stride 43, gcd(43,16)=1
#define SH   84
#define MST  17               // per-strip mid row stride in u64 (odd)
#define STRIPSZ (84*MST)      // u64 per strip mid
#define NTH  256
#define NPASS 11
#define WSUM 123
#define SMEM_BYTES (SH*SWP*4 + 4*STRIPSZ*8 + WSUM*8)

typedef unsigned long long u64;

// pass table: pairs of equal-K filters (filter i has K=KS[i], sigma=0.5+0.025i)
__constant__ int P_FA[NPASS]  = {0,3,5,7,9,11,13,15,17,19,2};
__constant__ int P_FB[NPASS]  = {1,4,6,8,10,12,14,16,18,20,2};
__constant__ int P_K [NPASS]  = {3,5,7,9,11,13,15,17,19,21,3};
__constant__ int P_OFF[NPASS] = {0,3,8,15,24,35,48,63,80,99,120};

__device__ __forceinline__ u64 pack2(float lo, float hi) {
    u64 d; asm("mov.b64 %0, {%1, %2};" : "=l"(d) : "f"(lo), "f"(hi)); return d;
}
__device__ __forceinline__ void fma2(u64& d, u64 a, u64 b) {
    asm("fma.rn.f32x2 %0, %1, %2, %0;" : "+l"(d) : "l"(a), "l"(b));
}
union F2 { u64 u; float2 f; };

__device__ __forceinline__ void bar64(int sid) {
    asm volatile("bar.sync %0, 64;" :: "r"(sid) : "memory");
}

__device__ __forceinline__ int refl(int v) {
    if (v < 0)    v = -v;
    if (v >= 512) v = 1022 - v;
    return v;
}

// One pass = two same-K filters in f32x2 lanes. 2-warp strip (16 cols):
// top warp H rows [0,H1), bottom [H1,MROWS); bar64 between H and V phases.
template<int K>
__device__ __forceinline__ void blur_pair(const float* __restrict__ s_in,
                                          u64* __restrict__ smid,
                                          const u64* __restrict__ w2,
                                          float* __restrict__ outA,
                                          float* __restrict__ outB,
                                          bool dualB, int x0, int y0,
                                          int lane, int half, int c0, int sid) {
    constexpr int R     = (K - 1) / 2;
    constexpr int MROWS = K + 63;
    constexpr int H1    = (MROWS + 1) / 2;     // <= 42
    constexpr int HK    = (K + 1) / 2;
    constexpr int D1    = (RMAX - R) & 1;
    constexpr int NU    = (D1 + K + 16) / 2;   // u64 covering D1+K+15 floats

    u64 wr[HK];
    #pragma unroll
    for (int j = 0; j < HK; ++j) wr[j] = w2[j];

    // ---- horizontal: each lane = one mid row x 16 cols, streaming 4-u64 ring ----
    {
        int start = half ? H1 : 0;
        int cnt   = half ? (MROWS - H1) : H1;
        #pragma unroll
        for (int rb = 0; rb < 64; rb += 32) {
            int rl = rb + lane;
            if (rl < cnt) {
                int r = start + rl;
                const u64* rp = (const u64*)s_in
                    + (size_t)(r + (RMAX - R)) * (SWP / 2)
                    + ((c0 + RMAX - R) >> 1);
                union { u64 u[4]; float f[8]; } ring;
                ring.u[0] = rp[0]; ring.u[1] = rp[1];
                ring.u[2] = rp[2]; ring.u[3] = rp[3];
                u64 a[16];
                #pragma unroll
                for (int j = 0; j < 16; ++j) a[j] = 0;
                #pragma unroll
                for (int e = 0; e < K + 15; ++e) {
                    int ph = D1 + e;
                    if (ph >= 8 && (ph & 3) == 0) {
                        int j = ph >> 1;
                        if (j < NU)     ring.u[j & 3]       = rp[j];
                        if (j + 1 < NU) ring.u[(j + 1) & 3] = rp[j + 1];
                    }
                    float v = ring.f[ph & 7];
                    u64 p = pack2(v, v);
                    #pragma unroll
                    for (int j = 0; j < 16; ++j) {
                        int t = e - j;
                        if (t >= 0 && t < K)
                            fma2(a[j], wr[(t < HK) ? t : (K - 1 - t)], p);
                    }
                }
                u64* dst = smid + r * MST;
                #pragma unroll
                for (int j = 0; j < 16; ++j)
                    dst[j] = a[j];               // STS.64, 2-per-wide-bank floor
            }
        }
    }
    bar64(sid);   // strip's mid complete

    // ---- vertical: lane = (c 0..15, rg 0..1), 16 rows x 1 col ----
    {
        int c  = lane & 15, rg = lane >> 4;
        int R0g = 32 * half + 16 * rg;
        const u64* mp = smid + R0g * MST + c;
        u64 acc[16];
        #pragma unroll
        for (int rr = 0; rr < 16; ++rr) acc[rr] = 0;
        #pragma unroll
        for (int m = 0; m < K + 15; ++m) {
            u64 val = mp[m * MST];               // LDS.64, 2-per-wide-bank floor
            #pragma unroll
            for (int rr = 0; rr < 16; ++rr) {
                int t = m - rr;
                if (t >= 0 && t < K)
                    fma2(acc[rr], wr[(t < HK) ? t : (K - 1 - t)], val);
            }
        }
        float* oa = outA + (size_t)(y0 + R0g) * W + (x0 + c0 + c);
        float* ob = outB + (size_t)(y0 + R0g) * W + (x0 + c0 + c);
        if (dualB) {
            #pragma unroll
            for (int rr = 0; rr < 16; ++rr) {
                F2 f; f.u = acc[rr];
                oa[(size_t)rr * W] = f.f.x;       // 2 lines/instr now
                ob[(size_t)rr * W] = f.f.y;
            }
        } else {
            #pragma unroll
            for (int rr = 0; rr < 16; ++rr) {
                F2 f; f.u = acc[rr];
                oa[(size_t)rr * W] = f.f.x;
            }
        }
    }
    bar64(sid);   // V reads done before next pass's H overwrites mid
}

__global__ void __launch_bounds__(NTH, 3)
gauss_fused(const float* __restrict__ x, float* __restrict__ out) {
    extern __shared__ float smem[];
    float* s_in = smem;                          // SH*SWP floats
    u64*   midp = (u64*)(smem + SH * SWP);       // 4 strip buffers
    u64*   s_w2 = midp + 4 * STRIPSZ;            // WSUM weight pairs

    int tid = threadIdx.x;

    // per-pass paired weight generation (graph-capturable)
    if (tid < NPASS) {
        int K = P_K[tid];
        int fa = P_FA[tid], fb = P_FB[tid];
        int off = P_OFF[tid];
        float sa = 0.5f + 0.025f * fa;
        float sb = 0.5f + 0.025f * fb;
        float s2a = 2.0f * sa * sa, s2b = 2.0f * sb * sb;
        int h = K / 2;
        float suma = 0.0f, sumb = 0.0f;
        for (int j = 0; j < K; ++j) {
            float d = (float)(j - h);
            suma += expf(-d * d / s2a);
            sumb += expf(-d * d / s2b);
        }
        for (int j = 0; j < K; ++j) {
            float d = (float)(j - h);
            s_w2[off + j] = pack2(expf(-d * d / s2a) / suma,
                                  expf(-d * d / s2b) / sumb);
        }
    }

    int z = blockIdx.z;                 // b*3 + c
    int b = z / 3, cch = z - 3 * b;
    int x0 = blockIdx.x * TW, y0 = blockIdx.y * TH;
    const float* xin = x + (size_t)z * HW;

    // load 84x84 halo tile once into padded-stride smem
    bool interior = (x0 != 0) && (x0 != W - TW) && (y0 != 0) && (y0 != HGT - TH);
    if (interior) {
        const float* base = xin + (size_t)(y0 - RMAX) * W + (x0 - RMAX);
        for (int idx = tid; idx < SH * SW; idx += NTH) {
            int ly = idx / SW, lx = idx - ly * SW;
            s_in[ly * SWP + lx] = base[ly * W + lx];
        }
    } else {
        for (int idx = tid; idx < SH * SW; idx += NTH) {
            int ly = idx / SW, lx = idx - ly * SW;
            int gy = refl(y0 + ly - RMAX);
            int gx = refl(x0 + lx - RMAX);
            s_in[ly * SWP + lx] = xin[gy * W + gx];
        }
    }

    // identity channel: copy this tile of x into out[b*66+cch]
    {
        const float4* src = (const float4*)(xin + (size_t)y0 * W + x0);
        float4* dst = (float4*)(out + (size_t)(b * 66 + cch) * HW + (size_t)y0 * W + x0);
        #pragma unroll
        for (int i = tid; i < TH * (TW / 4); i += NTH) {
            int r = i >> 4, q = i & 15;
            dst[r * (W / 4) + q] = src[r * (W / 4) + q];
        }
    }
    __syncthreads();   // the only block-wide barrier

    int lane  = tid & 31;
    int wid   = tid >> 5;
    int strip = wid >> 1;               // 4 strips of 16 columns
    int half  = wid & 1;                // top/bottom H rows, V row halves
    int c0    = strip * 16;
    int sid   = 1 + strip;              // named barrier per strip
    u64* smid = midp + strip * STRIPSZ;

    #pragma unroll 1
    for (int p = 0; p < NPASS; ++p) {
        int fa = P_FA[p], fb = P_FB[p];
        float* oA = out + (size_t)(b * 66 + 3 + 3 * fa + cch) * HW;
        float* oB = out + (size_t)(b * 66 + 3 + 3 * fb + cch) * HW;
        bool dualB = (fb != fa);
        const u64* w2 = s_w2 + P_OFF[p];
        switch (P_K[p]) {
            case 3:  blur_pair<3 >(s_in, smid, w2, oA, oB, dualB, x0, y0, lane, half, c0, sid); break;
            case 5:  blur_pair<5 >(s_in, smid, w2, oA, oB, dualB, x0, y0, lane, half, c0, sid); break;
            case 7:  blur_pair<7 >(s_in, smid, w2, oA, oB, dualB, x0, y0, lane, half, c0, sid); break;
            case 9:  blur_pair<9 >(s_in, smid, w2, oA, oB, dualB, x0, y0, lane, half, c0, sid); break;
            case 11: blur_pair<11>(s_in, smid, w2, oA, oB, dualB, x0, y0, lane, half, c0, sid); break;
            case 13: blur_pair<13>(s_in, smid, w2, oA, oB, dualB, x0, y0, lane, half, c0, sid); break;
            case 15: blur_pair<15>(s_in, smid, w2, oA, oB, dualB, x0, y0, lane, half, c0, sid); break;
            case 17: blur_pair<17>(s_in, smid, w2, oA, oB, dualB, x0, y0, lane, half, c0, sid); break;
            case 19: blur_pair<19>(s_in, smid, w2, oA, oB, dualB, x0, y0, lane, half, c0, sid); break;
            case 21: blur_pair<21>(s_in, smid, w2, oA, oB, dualB, x0, y0, lane, half, c0, sid); break;
        }
    }
}

extern "C" void kernel_launch(void* const* d_in, const int* in_sizes, int n_in,
                              void* d_out, int out_size) {
    const float* x = (const float*)d_in[0];
    float* out = (float*)d_out;

    cudaFuncSetAttribute(gauss_fused, cudaFuncAttributeMaxDynamicSharedMemorySize, SMEM_BYTES);

    dim3 grid(W / TW, HGT / TH, 24);    // 8 x 8 x 24
    gauss_fused<<<grid, NTH, SMEM_BYTES>>>(x, out);
}

// round 13
// speedup vs baseline: 1.1858x; 1.1858x over previous
#include <cuda_runtime.h>
#include <math.h>

#define W    512
#define HGT  512
#define HW   (512*512)
#define TW   64
#define TH   64
#define RMAX 10
#define SW   84               // logical halo tile width
#define SWP  86               // padded s_in row stride (words): u64 stride 43, gcd(43,16)=1
#define SH   84
#define MST  65               // mid row stride in u64 (odd: 65 mod 16 = 1)
#define NTH  256
#define NPASS 11
#define WSUM 123
#define SMEM_BYTES (SH*SWP*4 + SH*MST*8 + WSUM*8)

typedef unsigned long long u64;

// pass table: pairs of equal-K filters (filter i has K=KS[i], sigma=0.5+0.025i)
__constant__ int P_FA[NPASS]  = {0,3,5,7,9,11,13,15,17,19,2};
__constant__ int P_FB[NPASS]  = {1,4,6,8,10,12,14,16,18,20,2};
__constant__ int P_K [NPASS]  = {3,5,7,9,11,13,15,17,19,21,3};
__constant__ int P_OFF[NPASS] = {0,3,8,15,24,35,48,63,80,99,120};

__device__ __forceinline__ u64 pack2(float lo, float hi) {
    u64 d; asm("mov.b64 %0, {%1, %2};" : "=l"(d) : "f"(lo), "f"(hi)); return d;
}
__device__ __forceinline__ void fma2(u64& d, u64 a, u64 b) {
    asm("fma.rn.f32x2 %0, %1, %2, %0;" : "+l"(d) : "l"(a), "l"(b));
}
union F2 { u64 u; float2 f; };

__device__ __forceinline__ int refl(int v) {
    if (v < 0)    v = -v;
    if (v >= 512) v = 1022 - v;
    return v;
}

// One pass = two same-K filters packed in f32x2 lanes.
// H: warp-autonomous 8-column slice (R11 datapath). barrier.
// V: warp = 8 output rows x all 64 cols -> fully coalesced STG. barrier.
template<int K>
__device__ __forceinline__ void blur_pair(const float* __restrict__ s_in,
                                          u64* __restrict__ midp,
                                          const u64* __restrict__ w2,
                                          float* __restrict__ outA,
                                          float* __restrict__ outB,
                                          bool dualB, int x0, int y0,
                                          int lane, int wid, int c0) {
    constexpr int R     = (K - 1) / 2;
    constexpr int MROWS = K + 63;              // 66..84
    constexpr int HK    = (K + 1) / 2;
    constexpr int D1    = (RMAX - R) & 1;      // window start parity (c0 even)
    constexpr int NU    = (D1 + K + 8) / 2;    // u64 loads covering D1+K+7 floats

    u64 wr[HK];
    #pragma unroll
    for (int j = 0; j < HK; ++j) wr[j] = w2[j];

    // ---- horizontal: lane handles full rows of this warp's 8 logical columns ----
    #pragma unroll
    for (int rb = 0; rb < 96; rb += 32) {
        int r = rb + lane;
        bool act = (rb + 32 <= MROWS) || (r < MROWS);
        if (act) {
            const u64* rp = (const u64*)s_in + (size_t)(r + (RMAX - R)) * (SWP / 2)
                            + ((c0 + (RMAX - R)) >> 1);
            union { u64 u[NU]; float f[2 * NU]; } win;
            #pragma unroll
            for (int i = 0; i < NU; ++i) win.u[i] = rp[i];   // LDS.64, 2-wf floor

            u64 a[8];
            #pragma unroll
            for (int j = 0; j < 8; ++j) a[j] = 0;
            #pragma unroll
            for (int e = 0; e < K + 7; ++e) {
                float v = win.f[D1 + e];
                u64 p = pack2(v, v);
                #pragma unroll
                for (int j = 0; j < 8; ++j) {
                    int t = e - j;
                    if (t >= 0 && t < K)
                        fma2(a[j], wr[(t < HK) ? t : (K - 1 - t)], p);
                }
            }
            u64* dst = midp + r * MST + c0;       // banks (r + c0 + j) mod 16 -> floor
            #pragma unroll
            for (int j = 0; j < 8; ++j)
                dst[j] = a[j];
        }
    }
    __syncthreads();   // mid complete

    // ---- vertical: warp wid -> output rows [8*wid, 8*wid+8), cols = lane, lane+32 ----
    {
        int vr0 = wid * 8;
        u64 aA[8], aB[8];
        #pragma unroll
        for (int r = 0; r < 8; ++r) { aA[r] = 0; aB[r] = 0; }
        const u64* mp = midp + vr0 * MST + lane;
        #pragma unroll
        for (int m = 0; m < K + 7; ++m) {
            u64 vA = mp[m * MST];                 // LDS.64 consecutive lanes -> floor
            u64 vB = mp[m * MST + 32];
            #pragma unroll
            for (int r = 0; r < 8; ++r) {
                int t = m - r;
                if (t >= 0 && t < K) {
                    u64 w = wr[(t < HK) ? t : (K - 1 - t)];
                    fma2(aA[r], w, vA);
                    fma2(aB[r], w, vB);
                }
            }
        }
        float* oa = outA + (size_t)(y0 + vr0) * W + x0 + lane;
        float* ob = outB + (size_t)(y0 + vr0) * W + x0 + lane;
        if (dualB) {
            #pragma unroll
            for (int r = 0; r < 8; ++r) {
                F2 fa, fb; fa.u = aA[r]; fb.u = aB[r];
                oa[(size_t)r * W]      = fa.f.x;   // 1 line per STG
                oa[(size_t)r * W + 32] = fb.f.x;
                ob[(size_t)r * W]      = fa.f.y;
                ob[(size_t)r * W + 32] = fb.f.y;
            }
        } else {
            #pragma unroll
            for (int r = 0; r < 8; ++r) {
                F2 fa, fb; fa.u = aA[r]; fb.u = aB[r];
                oa[(size_t)r * W]      = fa.f.x;
                oa[(size_t)r * W + 32] = fb.f.x;
            }
        }
    }
    __syncthreads();   // V reads done before next pass's H overwrites mid
}

__global__ void __launch_bounds__(NTH, 3)
gauss_fused(const float* __restrict__ x, float* __restrict__ out) {
    extern __shared__ float smem[];
    float* s_in = smem;                          // SH*SWP floats (padded stride)
    u64*   midp = (u64*)(smem + SH * SWP);       // SH*MST u64 (plain layout)
    u64*   s_w2 = midp + SH * MST;               // WSUM weight pairs

    int tid = threadIdx.x;

    // per-pass paired weight generation (graph-capturable)
    if (tid < NPASS) {
        int K = P_K[tid];
        int fa = P_FA[tid], fb = P_FB[tid];
        int off = P_OFF[tid];
        float sa = 0.5f + 0.025f * fa;
        float sb = 0.5f + 0.025f * fb;
        float s2a = 2.0f * sa * sa, s2b = 2.0f * sb * sb;
        int h = K / 2;
        float suma = 0.0f, sumb = 0.0f;
        for (int j = 0; j < K; ++j) {
            float d = (float)(j - h);
            suma += expf(-d * d / s2a);
            sumb += expf(-d * d / s2b);
        }
        for (int j = 0; j < K; ++j) {
            float d = (float)(j - h);
            s_w2[off + j] = pack2(expf(-d * d / s2a) / suma,
                                  expf(-d * d / s2b) / sumb);
        }
    }

    int z = blockIdx.z;                 // b*3 + c
    int b = z / 3, cch = z - 3 * b;
    int x0 = blockIdx.x * TW, y0 = blockIdx.y * TH;
    const float* xin = x + (size_t)z * HW;

    // load 84x84 halo tile once into padded-stride smem
    bool interior = (x0 != 0) && (x0 != W - TW) && (y0 != 0) && (y0 != HGT - TH);
    if (interior) {
        const float* base = xin + (size_t)(y0 - RMAX) * W + (x0 - RMAX);
        for (int idx = tid; idx < SH * SW; idx += NTH) {
            int ly = idx / SW, lx = idx - ly * SW;
            s_in[ly * SWP + lx] = base[ly * W + lx];
        }
    } else {
        for (int idx = tid; idx < SH * SW; idx += NTH) {
            int ly = idx / SW, lx = idx - ly * SW;
            int gy = refl(y0 + ly - RMAX);
            int gx = refl(x0 + lx - RMAX);
            s_in[ly * SWP + lx] = xin[gy * W + gx];
        }
    }

    // identity channel: copy this tile of x into out[b*66+cch]
    {
        const float4* src = (const float4*)(xin + (size_t)y0 * W + x0);
        float4* dst = (float4*)(out + (size_t)(b * 66 + cch) * HW + (size_t)y0 * W + x0);
        #pragma unroll
        for (int i = tid; i < TH * (TW / 4); i += NTH) {
            int r = i >> 4, q = i & 15;
            dst[r * (W / 4) + q] = src[r * (W / 4) + q];
        }
    }
    __syncthreads();

    int lane = tid & 31;
    int wid  = tid >> 5;
    int c0   = wid * 8;                 // warp's H column slice

    #pragma unroll 1
    for (int p = 0; p < NPASS; ++p) {
        int fa = P_FA[p], fb = P_FB[p];
        float* oA = out + (size_t)(b * 66 + 3 + 3 * fa + cch) * HW;
        float* oB = out + (size_t)(b * 66 + 3 + 3 * fb + cch) * HW;
        bool dualB = (fb != fa);
        const u64* w2 = s_w2 + P_OFF[p];
        switch (P_K[p]) {
            case 3:  blur_pair<3 >(s_in, midp, w2, oA, oB, dualB, x0, y0, lane, wid, c0); break;
            case 5:  blur_pair<5 >(s_in, midp, w2, oA, oB, dualB, x0, y0, lane, wid, c0); break;
            case 7:  blur_pair<7 >(s_in, midp, w2, oA, oB, dualB, x0, y0, lane, wid, c0); break;
            case 9:  blur_pair<9 >(s_in, midp, w2, oA, oB, dualB, x0, y0, lane, wid, c0); break;
            case 11: blur_pair<11>(s_in, midp, w2, oA, oB, dualB, x0, y0, lane, wid, c0); break;
            case 13: blur_pair<13>(s_in, midp, w2, oA, oB, dualB, x0, y0, lane, wid, c0); break;
            case 15: blur_pair<15>(s_in, midp, w2, oA, oB, dualB, x0, y0, lane, wid, c0); break;
            case 17: blur_pair<17>(s_in, midp, w2, oA, oB, dualB, x0, y0, lane, wid, c0); break;
            case 19: blur_pair<19>(s_in, midp, w2, oA, oB, dualB, x0, y0, lane, wid, c0); break;
            case 21: blur_pair<21>(s_in, midp, w2, oA, oB, dualB, x0, y0, lane, wid, c0); break;
        }
    }
}

extern "C" void kernel_launch(void* const* d_in, const int* in_sizes, int n_in,
                              void* d_out, int out_size) {
    const float* x = (const float*)d_in[0];
    float* out = (float*)d_out;

    cudaFuncSetAttribute(gauss_fused, cudaFuncAttributeMaxDynamicSharedMemorySize, SMEM_BYTES);

    dim3 grid(W / TW, HGT / TH, 24);    // 8 x 8 x 24
    gauss_fused<<<grid, NTH, SMEM_BYTES>>>(x, out);
}

// round 14
// speedup vs baseline: 1.2739x; 1.0744x over previous
#include <cuda_runtime.h>
#include <math.h>

#define W    512
#define HGT  512
#define HW   (512*512)
#define TW   64
#define TH   64
#define RMAX 10
#define SW   84               // logical halo tile width
#define SWP  86               // padded s_in row stride (words): u64 stride 43, gcd(43,16)=1
#define SH   84
#define MST  65               // mid row stride in u64 (odd)
#define NTH  256
#define NPASS 11
#define WSUM 123
#define NTILE 1536            // 8 x 8 x 24
#define NCTA  444             // 148 SMs x 3 CTAs -> one wave, persistent
#define SMEM_BYTES (SH*SWP*4 + SH*MST*8 + WSUM*8)

typedef unsigned long long u64;

// pass table: pairs of equal-K filters (filter i has K=KS[i], sigma=0.5+0.025i)
__constant__ int P_FA[NPASS]  = {0,3,5,7,9,11,13,15,17,19,2};
__constant__ int P_FB[NPASS]  = {1,4,6,8,10,12,14,16,18,20,2};
__constant__ int P_K [NPASS]  = {3,5,7,9,11,13,15,17,19,21,3};
__constant__ int P_OFF[NPASS] = {0,3,8,15,24,35,48,63,80,99,120};

__device__ __forceinline__ u64 pack2(float lo, float hi) {
    u64 d; asm("mov.b64 %0, {%1, %2};" : "=l"(d) : "f"(lo), "f"(hi)); return d;
}
__device__ __forceinline__ void fma2(u64& d, u64 a, u64 b) {
    asm("fma.rn.f32x2 %0, %1, %2, %0;" : "+l"(d) : "l"(a), "l"(b));
}
union F2 { u64 u; float2 f; };

__device__ __forceinline__ int refl(int v) {
    if (v < 0)    v = -v;
    if (v >= 512) v = 1022 - v;
    return v;
}

// One pass = two same-K filters packed in f32x2 lanes. Fully warp-local.
// mid physical column = (logical_col + 4*(row>>4)) & 63 -> 64-bit smem ops at bank floor.
template<int K>
__device__ __forceinline__ void blur_pair(const float* __restrict__ s_in,
                                          u64* __restrict__ midp,
                                          const u64* __restrict__ w2,
                                          float* __restrict__ outA,
                                          float* __restrict__ outB,
                                          bool dualB,
                                          int x0, int y0, int lane, int c0) {
    constexpr int R     = (K - 1) / 2;
    constexpr int MROWS = TH + 2 * R;          // 66..84
    constexpr int HK    = (K + 1) / 2;
    constexpr int D1    = (RMAX - R) & 1;      // window start parity (c0 is even)
    constexpr int NU    = (K + 8 + D1) / 2;    // u64 loads covering K+7 floats

    u64 wr[HK];
    #pragma unroll
    for (int j = 0; j < HK; ++j) wr[j] = w2[j];

    // ---- horizontal: lane handles full rows of its 8 logical columns ----
    #pragma unroll
    for (int rb = 0; rb < 96; rb += 32) {
        int r = rb + lane;
        bool act = (rb + 32 <= MROWS) || (r < MROWS);
        if (act) {
            const u64* rp = (const u64*)s_in + (size_t)(r + (RMAX - R)) * (SWP / 2)
                            + ((c0 + (RMAX - R)) >> 1);
            union { u64 u[NU]; float f[2 * NU]; } win;
            #pragma unroll
            for (int i = 0; i < NU; ++i) win.u[i] = rp[i];   // LDS.64, 2-wf floor

            u64 a[8];
            #pragma unroll
            for (int j = 0; j < 8; ++j) a[j] = 0;
            #pragma unroll
            for (int e = 0; e < K + 7; ++e) {
                float v = win.f[D1 + e];
                u64 p = pack2(v, v);
                #pragma unroll
                for (int j = 0; j < 8; ++j) {
                    int t = e - j;
                    if (t >= 0 && t < K)
                        fma2(a[j], wr[(t < HK) ? t : (K - 1 - t)], p);
                }
            }
            u64* dst = midp + r * MST;
            int rot = c0 + 4 * (r >> 4);         // row-dependent rotation
            #pragma unroll
            for (int j = 0; j < 8; ++j)
                dst[(rot + j) & 63] = a[j];      // STS.64, 2-per-wide-bank floor
        }
    }
    __syncwarp();

    // ---- vertical: lane = (c 0..7, rg 0..3), 16 rows x 1 col ----
    {
        int c  = lane & 7, rg = lane >> 3;
        int r0 = rg << 4;
        int cbase = c0 + c + 4 * rg;             // rotation at row r0+m adds 4*(m>>4)
        const u64* mp = midp + r0 * MST;
        u64 acc[16];
        #pragma unroll
        for (int rr = 0; rr < 16; ++rr) acc[rr] = 0;
        #pragma unroll
        for (int m = 0; m < K + 15; ++m) {
            int colp = (cbase + 4 * (m >> 4)) & 63;   // m compile-time -> folds
            u64 val = mp[m * MST + colp];             // LDS.64, 2-per-wide-bank floor
            #pragma unroll
            for (int rr = 0; rr < 16; ++rr) {
                int t = m - rr;
                if (t >= 0 && t < K)
                    fma2(acc[rr], wr[(t < HK) ? t : (K - 1 - t)], val);
            }
        }
        float* oa = outA + (size_t)(y0 + r0) * W + (x0 + c0 + c);
        float* ob = outB + (size_t)(y0 + r0) * W + (x0 + c0 + c);
        if (dualB) {
            #pragma unroll
            for (int rr = 0; rr < 16; ++rr) {
                F2 f; f.u = acc[rr];
                oa[(size_t)rr * W] = f.f.x;
                ob[(size_t)rr * W] = f.f.y;
            }
        } else {
            #pragma unroll
            for (int rr = 0; rr < 16; ++rr) {
                F2 f; f.u = acc[rr];
                oa[(size_t)rr * W] = f.f.x;
            }
        }
    }
    __syncwarp();
}

__global__ void __launch_bounds__(NTH, 3)
gauss_fused(const float* __restrict__ x, float* __restrict__ out) {
    extern __shared__ float smem[];
    float* s_in = smem;                          // SH*SWP floats (padded stride)
    u64*   midp = (u64*)(smem + SH * SWP);       // SH*MST u64 (rotated layout)
    u64*   s_w2 = midp + SH * MST;               // WSUM weight pairs

    int tid = threadIdx.x;

    // per-pass paired weight generation, once per persistent CTA
    if (tid < NPASS) {
        int K = P_K[tid];
        int fa = P_FA[tid], fb = P_FB[tid];
        int off = P_OFF[tid];
        float sa = 0.5f + 0.025f * fa;
        float sb = 0.5f + 0.025f * fb;
        float s2a = 2.0f * sa * sa, s2b = 2.0f * sb * sb;
        int h = K / 2;
        float suma = 0.0f, sumb = 0.0f;
        for (int j = 0; j < K; ++j) {
            float d = (float)(j - h);
            suma += expf(-d * d / s2a);
            sumb += expf(-d * d / s2b);
        }
        for (int j = 0; j < K; ++j) {
            float d = (float)(j - h);
            s_w2[off + j] = pack2(expf(-d * d / s2a) / suma,
                                  expf(-d * d / s2b) / sumb);
        }
    }

    int lane = tid & 31;
    int c0   = (tid >> 5) * 8;          // warp's logical column slice

    // persistent loop over tiles
    #pragma unroll 1
    for (int t = blockIdx.x; t < NTILE; t += NCTA) {
        int z   = t >> 6;               // plane: b*3 + c
        int rem = t & 63;
        int by  = rem >> 3, bx = rem & 7;
        int b = z / 3, cch = z - 3 * b;
        int x0 = bx * TW, y0 = by * TH;
        const float* xin = x + (size_t)z * HW;

        __syncthreads();   // prior tile's passes done before overwriting s_in/mid

        // load 84x84 halo tile into padded-stride smem
        bool interior = (x0 != 0) && (x0 != W - TW) && (y0 != 0) && (y0 != HGT - TH);
        if (interior) {
            const float* base = xin + (size_t)(y0 - RMAX) * W + (x0 - RMAX);
            for (int idx = tid; idx < SH * SW; idx += NTH) {
                int ly = idx / SW, lx = idx - ly * SW;
                s_in[ly * SWP + lx] = base[ly * W + lx];
            }
        } else {
            for (int idx = tid; idx < SH * SW; idx += NTH) {
                int ly = idx / SW, lx = idx - ly * SW;
                int gy = refl(y0 + ly - RMAX);
                int gx = refl(x0 + lx - RMAX);
                s_in[ly * SWP + lx] = xin[gy * W + gx];
            }
        }

        // identity channel: copy this tile of x into out[b*66+cch]
        {
            const float4* src = (const float4*)(xin + (size_t)y0 * W + x0);
            float4* dst = (float4*)(out + (size_t)(b * 66 + cch) * HW + (size_t)y0 * W + x0);
            #pragma unroll
            for (int i = tid; i < TH * (TW / 4); i += NTH) {
                int r = i >> 4, q = i & 15;
                dst[r * (W / 4) + q] = src[r * (W / 4) + q];
            }
        }
        __syncthreads();   // s_in ready

        #pragma unroll 1
        for (int p = 0; p < NPASS; ++p) {
            int fa = P_FA[p], fb = P_FB[p];
            float* oA = out + (size_t)(b * 66 + 3 + 3 * fa + cch) * HW;
            float* oB = out + (size_t)(b * 66 + 3 + 3 * fb + cch) * HW;
            bool dualB = (fb != fa);
            const u64* w2 = s_w2 + P_OFF[p];
            switch (P_K[p]) {
                case 3:  blur_pair<3 >(s_in, midp, w2, oA, oB, dualB, x0, y0, lane, c0); break;
                case 5:  blur_pair<5 >(s_in, midp, w2, oA, oB, dualB, x0, y0, lane, c0); break;
                case 7:  blur_pair<7 >(s_in, midp, w2, oA, oB, dualB, x0, y0, lane, c0); break;
                case 9:  blur_pair<9 >(s_in, midp, w2, oA, oB, dualB, x0, y0, lane, c0); break;
                case 11: blur_pair<11>(s_in, midp, w2, oA, oB, dualB, x0, y0, lane, c0); break;
                case 13: blur_pair<13>(s_in, midp, w2, oA, oB, dualB, x0, y0, lane, c0); break;
                case 15: blur_pair<15>(s_in, midp, w2, oA, oB, dualB, x0, y0, lane, c0); break;
                case 17: blur_pair<17>(s_in, midp, w2, oA, oB, dualB, x0, y0, lane, c0); break;
                case 19: blur_pair<19>(s_in, midp, w2, oA, oB, dualB, x0, y0, lane, c0); break;
                case 21: blur_pair<21>(s_in, midp, w2, oA, oB, dualB, x0, y0, lane, c0); break;
            }
        }
    }
}

extern "C" void kernel_launch(void* const* d_in, const int* in_sizes, int n_in,
                              void* d_out, int out_size) {
    const float* x = (const float*)d_in[0];
    float* out = (float*)d_out;

    cudaFuncSetAttribute(gauss_fused, cudaFuncAttributeMaxDynamicSharedMemorySize, SMEM_BYTES);

    gauss_fused<<<NCTA, NTH, SMEM_BYTES>>>(x, out);   // persistent: 444 CTAs, one wave
}